// round 14
// baseline (speedup 1.0000x reference)
#include <cuda_runtime.h>
#include <cuda_fp16.h>
#include <cstdint>

#define B_SESS 4096
#define MAX_LEN 200
#define E 112
#define N_ITEMS 100000
#define LAYERS 3
#define KSPLIT 8
#define KCHUNK (B_SESS / KSPLIT)   // 512
#define BK 32
#define NSTAGE (KCHUNK / BK)       // 16

// big_mm smem (halves): 3-stage ring; strides conflict-free for half2 LDS.
#define AS_H 40
#define BS_H 40
#define A_STAGE_H (128 * AS_H)     // 5120 halves
#define B_STAGE_H (E * BS_H)       // 4480 halves
#define SMEM_BYTES ((3 * A_STAGE_H + 3 * B_STAGE_H) * 2)   // 57600

// small_mm smem: S tile [32][116], W^T [112][120] (tf32 bits)
#define SS_STRIDE 116
#define WS_STRIDE 120
#define SM2_BYTES ((32 * SS_STRIDE + 112 * WS_STRIDE) * 4)   // 68608

// prep grid partition (896 threads/CTA): gather || A->fp16 || diag
#define PREP_T 896
#define NB_GATHER 4096
#define NB_CVTA   2341               // ceil(16777216 / (896*8))
#define NB_DIAG   5
#define NB_PREP   (NB_GATHER + NB_CVTA + NB_DIAG)

// Scratch
__device__ __half g_Ah[(size_t)B_SESS * B_SESS];     // A in fp16
__device__ __half g_tT[(size_t)E * B_SESS];          // (s @ W^T)^T fp16 [112,4096]
__device__ float g_s[B_SESS * E];
__device__ float g_acc[B_SESS * E];
__device__ __half g_part[(size_t)KSPLIT * B_SESS * E];  // fp16 split-K partials
__device__ float g_d[B_SESS];

// ---------------------------------------------------------------------------
// PTX helpers (plain sm_80+; no arch-'a' gating)
// ---------------------------------------------------------------------------
__device__ __forceinline__ uint32_t smem_u32(const void* p) {
    uint32_t a;
    asm("{ .reg .u64 t; cvta.to.shared.u64 t, %1; cvt.u32.u64 %0, t; }"
        : "=r"(a) : "l"(p));
    return a;
}
__device__ __forceinline__ uint32_t f2tf32(float f) {
    uint32_t u;
    asm("cvt.rn.tf32.f32 %0, %1;" : "=r"(u) : "f"(f));
    return u;
}
#define CP16(dst, src) \
    asm volatile("cp.async.cg.shared.global [%0], [%1], 16;" \
                 :: "r"(dst), "l"(src) : "memory")
#define CP_COMMIT() asm volatile("cp.async.commit_group;" ::: "memory")
#define CP_WAIT2()  asm volatile("cp.async.wait_group 2;" ::: "memory")
#define CP_WAIT1()  asm volatile("cp.async.wait_group 1;" ::: "memory")
#define CP_WAIT0()  asm volatile("cp.async.wait_group 0;" ::: "memory")

// tf32 k8 mma (small_mm)
__device__ __forceinline__ void mma_tf32(float* c, const uint32_t* a,
                                         const uint32_t* b) {
    asm volatile(
        "mma.sync.aligned.m16n8k8.row.col.f32.tf32.tf32.f32 "
        "{%0,%1,%2,%3},{%4,%5,%6,%7},{%8,%9},{%0,%1,%2,%3};"
        : "+f"(c[0]), "+f"(c[1]), "+f"(c[2]), "+f"(c[3])
        : "r"(a[0]), "r"(a[1]), "r"(a[2]), "r"(a[3]), "r"(b[0]), "r"(b[1]));
}
// fp16 k16 mma (big_mm)
__device__ __forceinline__ void mma_f16(float* c, const uint32_t* a,
                                        const uint32_t* b) {
    asm volatile(
        "mma.sync.aligned.m16n8k16.row.col.f32.f16.f16.f32 "
        "{%0,%1,%2,%3},{%4,%5,%6,%7},{%8,%9},{%0,%1,%2,%3};"
        : "+f"(c[0]), "+f"(c[1]), "+f"(c[2]), "+f"(c[3])
        : "r"(a[0]), "r"(a[1]), "r"(a[2]), "r"(a[3]), "r"(b[0]), "r"(b[1]));
}

// ---------------------------------------------------------------------------
// 1. Prep: gather+mean (8-way time split, 896 thr) || A->fp16 || diag.
// ---------------------------------------------------------------------------
__global__ void __launch_bounds__(PREP_T)
prep_kernel(const float* __restrict__ A,
            const float* __restrict__ emb,
            const int* __restrict__ items,
            const float* __restrict__ slen,
            const float* __restrict__ D) {
    int blk = blockIdx.x;
    int tid = threadIdx.x;

    if (blk < NB_GATHER) {                       // ---- gather + mean pool ----
        __shared__ int sidx[MAX_LEN];
        __shared__ float partial[7][E];
        int b = blk;
        for (int i = tid; i < MAX_LEN; i += PREP_T)
            sidx[i] = items[(size_t)b * MAX_LEN + i];
        __syncthreads();
        int q = tid / E;                         // eighth 0..7
        int col = tid - q * E;
        float acc = 0.0f;
        {
            int t0 = q * (MAX_LEN / 8);
            int t1 = t0 + (MAX_LEN / 8);
            #pragma unroll 5
            for (int t = t0; t < t1; ++t) {
                int idx = sidx[t];
                if (idx > 0 && idx <= N_ITEMS)
                    acc += emb[((size_t)(idx - 1)) * E + col];
            }
        }
        if (q > 0) partial[q - 1][col] = acc;
        __syncthreads();
        if (q == 0) {
            #pragma unroll
            for (int j = 0; j < 7; ++j) acc += partial[j][col];
            float v = acc / slen[b];
            g_s[(size_t)b * E + col] = v;
            g_acc[(size_t)b * E + col] = v;
        }
    } else if (blk < NB_GATHER + NB_CVTA) {      // ---- A -> fp16 ----
        size_t i = (((size_t)(blk - NB_GATHER)) * PREP_T + tid) * 8;
        if (i < (size_t)B_SESS * B_SESS) {
            float4 a = *reinterpret_cast<const float4*>(A + i);
            float4 b = *reinterpret_cast<const float4*>(A + i + 4);
            __half2 h0 = __floats2half2_rn(a.x, a.y);
            __half2 h1 = __floats2half2_rn(a.z, a.w);
            __half2 h2 = __floats2half2_rn(b.x, b.y);
            __half2 h3 = __floats2half2_rn(b.z, b.w);
            uint4 u;
            u.x = *reinterpret_cast<uint32_t*>(&h0);
            u.y = *reinterpret_cast<uint32_t*>(&h1);
            u.z = *reinterpret_cast<uint32_t*>(&h2);
            u.w = *reinterpret_cast<uint32_t*>(&h3);
            *reinterpret_cast<uint4*>(&g_Ah[i]) = u;
        }
    } else {                                     // ---- diag(D) ----
        int i = (blk - NB_GATHER - NB_CVTA) * PREP_T + tid;
        if (i < B_SESS)
            g_d[i] = D[(size_t)i * B_SESS + i];
    }
}

// ---------------------------------------------------------------------------
// 2. small GEMM (tf32 tensor cores): g_tT = fp16((g_s @ W^T)^T)
//    grid 128 x 128 thr (4 warps: 2(M) x 2(N)). M=32/CTA, N=112, K=112.
// ---------------------------------------------------------------------------
__global__ void __launch_bounds__(128)
small_mm_tc(const float* __restrict__ W) {
    extern __shared__ uint32_t sm2[];
    uint32_t* Ss = sm2;                          // [32][SS_STRIDE]
    uint32_t* Wt = sm2 + 32 * SS_STRIDE;         // [112][WS_STRIDE] (k-major)

    const int tid = threadIdx.x;
    const int lane = tid & 31;
    const int wid = tid >> 5;
    const int wm = wid & 1;
    const int wn = wid >> 1;
    const int g = lane >> 2;
    const int t = lane & 3;
    const int row0 = blockIdx.x * 32;

    for (int idx = tid; idx < 32 * (E / 4); idx += 128) {
        int r = idx / (E / 4), c4 = idx % (E / 4);
        float4 v = *reinterpret_cast<const float4*>(
            &g_s[(size_t)(row0 + r) * E + c4 * 4]);
        uint32_t* dst = &Ss[r * SS_STRIDE + c4 * 4];
        dst[0] = f2tf32(v.x); dst[1] = f2tf32(v.y);
        dst[2] = f2tf32(v.z); dst[3] = f2tf32(v.w);
    }
    for (int idx = tid; idx < E * (E / 4); idx += 128) {
        int o = idx / (E / 4), i4 = idx % (E / 4);
        float4 v = *reinterpret_cast<const float4*>(&W[(size_t)o * E + i4 * 4]);
        Wt[(i4 * 4 + 0) * WS_STRIDE + o] = f2tf32(v.x);
        Wt[(i4 * 4 + 1) * WS_STRIDE + o] = f2tf32(v.y);
        Wt[(i4 * 4 + 2) * WS_STRIDE + o] = f2tf32(v.z);
        Wt[(i4 * 4 + 3) * WS_STRIDE + o] = f2tf32(v.w);
    }
    __syncthreads();

    float acc[7][4];
    #pragma unroll
    for (int j = 0; j < 7; ++j)
        #pragma unroll
        for (int k = 0; k < 4; ++k) acc[j][k] = 0.0f;

    #pragma unroll
    for (int ks = 0; ks < 14; ++ks) {
        uint32_t a[4], b[7][2];
        {
            int r = wm * 16 + g;
            int c = ks * 8 + t;
            a[0] = Ss[r * SS_STRIDE + c];
            a[1] = Ss[(r + 8) * SS_STRIDE + c];
            a[2] = Ss[r * SS_STRIDE + c + 4];
            a[3] = Ss[(r + 8) * SS_STRIDE + c + 4];
        }
        #pragma unroll
        for (int j = 0; j < 7; ++j) {
            int n = wn * 56 + j * 8 + g;
            int r = ks * 8 + t;
            b[j][0] = Wt[r * WS_STRIDE + n];
            b[j][1] = Wt[(r + 4) * WS_STRIDE + n];
        }
        #pragma unroll
        for (int j = 0; j < 7; ++j)
            mma_tf32(acc[j], a, b[j]);
    }

    // transposed fp16 store: g_tT[n][k]  (k = session row)
    {
        int r = row0 + wm * 16 + g;
        #pragma unroll
        for (int j = 0; j < 7; ++j) {
            int n = wn * 56 + j * 8 + 2 * t;
            g_tT[(size_t)n * B_SESS + r]           = __float2half(acc[j][0]);
            g_tT[(size_t)(n + 1) * B_SESS + r]     = __float2half(acc[j][1]);
            g_tT[(size_t)n * B_SESS + r + 8]       = __float2half(acc[j][2]);
            g_tT[(size_t)(n + 1) * B_SESS + r + 8] = __float2half(acc[j][3]);
        }
    }
}

// ---------------------------------------------------------------------------
// 3. Big fp16 tensor-core GEMM (3-stage cp.async): part = A[:,kc] @ t[kc,:]
// ---------------------------------------------------------------------------
__global__ void __launch_bounds__(256)
big_mm_mma() {
    extern __shared__ __half smemh[];
    __half* As = smemh;                      // [3][128][AS_H]
    __half* Bs = smemh + 3 * A_STAGE_H;      // [3][112][BS_H]

    const int tid = threadIdx.x;
    const int lane = tid & 31;
    const int wid = tid >> 5;
    const int wm = wid & 3;
    const int wn = wid >> 2;
    const int g = lane >> 2;
    const int t = lane & 3;
    const int row0 = blockIdx.x * 128;
    const int kbase = blockIdx.y * KCHUNK;

    float acc[2][7][4];
    #pragma unroll
    for (int i = 0; i < 2; ++i)
        #pragma unroll
        for (int j = 0; j < 7; ++j)
            #pragma unroll
            for (int k = 0; k < 4; ++k) acc[i][j][k] = 0.0f;

    auto stage = [&](int buf, int k0) {
        __half* Ab = As + buf * A_STAGE_H;
        __half* Bb = Bs + buf * B_STAGE_H;
        #pragma unroll
        for (int j = 0; j < 2; ++j) {          // A: 512 16B chunks
            int c = tid + j * 256;
            int r = c >> 2, cc = c & 3;
            uint32_t dst = smem_u32(&Ab[r * AS_H + cc * 8]);
            CP16(dst, &g_Ah[(size_t)(row0 + r) * B_SESS + k0 + cc * 8]);
        }
        #pragma unroll
        for (int j = 0; j < 2; ++j) {          // B: 448 16B chunks
            int c = tid + j * 256;
            if (c < 448) {
                int n = c >> 2, cc = c & 3;
                uint32_t dst = smem_u32(&Bb[n * BS_H + cc * 8]);
                CP16(dst, &g_tT[(size_t)n * B_SESS + k0 + cc * 8]);
            }
        }
    };

    auto compute = [&](int buf) {
        const __half* A_ = As + buf * A_STAGE_H;
        const __half* B_ = Bs + buf * B_STAGE_H;
        #pragma unroll
        for (int ks = 0; ks < 2; ++ks) {       // BK=32 -> 2 x K=16
            uint32_t a[2][4], b[7][2];
            #pragma unroll
            for (int i = 0; i < 2; ++i) {
                int r = wm * 32 + i * 16 + g;
                int c = ks * 16 + t * 2;
                a[i][0] = *reinterpret_cast<const uint32_t*>(&A_[r * AS_H + c]);
                a[i][1] = *reinterpret_cast<const uint32_t*>(&A_[(r + 8) * AS_H + c]);
                a[i][2] = *reinterpret_cast<const uint32_t*>(&A_[r * AS_H + c + 8]);
                a[i][3] = *reinterpret_cast<const uint32_t*>(&A_[(r + 8) * AS_H + c + 8]);
            }
            #pragma unroll
            for (int j = 0; j < 7; ++j) {
                int n = wn * 56 + j * 8 + g;
                int c = ks * 16 + t * 2;
                b[j][0] = *reinterpret_cast<const uint32_t*>(&B_[n * BS_H + c]);
                b[j][1] = *reinterpret_cast<const uint32_t*>(&B_[n * BS_H + c + 8]);
            }
            #pragma unroll
            for (int i = 0; i < 2; ++i)
                #pragma unroll
                for (int j = 0; j < 7; ++j)
                    mma_f16(acc[i][j], a[i], b[j]);
        }
    };

    stage(0, kbase);
    CP_COMMIT();
    stage(1, kbase + BK);
    CP_COMMIT();
    int buf = 0;
    for (int s = 0; s < NSTAGE; ++s) {
        if (s + 2 < NSTAGE) {
            stage((s + 2) % 3, kbase + (s + 2) * BK);
            CP_COMMIT();
            CP_WAIT2();
        } else if (s + 1 < NSTAGE) {
            CP_WAIT1();
        } else {
            CP_WAIT0();
        }
        __syncthreads();
        compute(buf);
        if (++buf == 3) buf = 0;
        __syncthreads();
    }

    // fp16 partial stores (half2 per n-pair)
    __half* part = g_part + (size_t)blockIdx.y * B_SESS * E;
    #pragma unroll
    for (int i = 0; i < 2; ++i) {
        int r = row0 + wm * 32 + i * 16 + g;
        #pragma unroll
        for (int j = 0; j < 7; ++j) {
            int n = wn * 56 + j * 8 + 2 * t;
            *reinterpret_cast<__half2*>(&part[(size_t)r * E + n]) =
                __floats2half2_rn(acc[i][j][0], acc[i][j][1]);
            *reinterpret_cast<__half2*>(&part[(size_t)(r + 8) * E + n]) =
                __floats2half2_rn(acc[i][j][2], acc[i][j][3]);
        }
    }
}

// ---------------------------------------------------------------------------
// 4. Fused: split-K reduce (fp16 partials) + diag scale + L2-normalize + acc
//    (+ final out). One warp per row; block = 8 warps; grid = 512.
// ---------------------------------------------------------------------------
__global__ void reduce_norm_kernel(float* __restrict__ out, int last) {
    int warp = threadIdx.x >> 5;
    int lane = threadIdx.x & 31;
    int r = blockIdx.x * 8 + warp;

    float4 v = make_float4(0.f, 0.f, 0.f, 0.f);
    if (lane < E / 4) {
        #pragma unroll
        for (int c = 0; c < KSPLIT; ++c) {
            uint2 u = *reinterpret_cast<const uint2*>(
                &g_part[(size_t)c * B_SESS * E + (size_t)r * E + lane * 4]);
            float2 p0 = __half22float2(*reinterpret_cast<__half2*>(&u.x));
            float2 p1 = __half22float2(*reinterpret_cast<__half2*>(&u.y));
            v.x += p0.x; v.y += p0.y; v.z += p1.x; v.w += p1.y;
        }
        float d = g_d[r];
        v.x *= d; v.y *= d; v.z *= d; v.w *= d;
        *reinterpret_cast<float4*>(&g_s[(size_t)r * E + lane * 4]) = v;
    }
    float ss = v.x * v.x + v.y * v.y + v.z * v.z + v.w * v.w;
    #pragma unroll
    for (int o = 16; o; o >>= 1) ss += __shfl_xor_sync(0xffffffffu, ss, o);
    float f = 1.0f / fmaxf(sqrtf(ss), 1e-12f);
    if (lane < E / 4) {
        float4* arow = reinterpret_cast<float4*>(g_acc + (size_t)r * E);
        float4 a = arow[lane];
        a.x = fmaf(v.x, f, a.x);
        a.y = fmaf(v.y, f, a.y);
        a.z = fmaf(v.z, f, a.z);
        a.w = fmaf(v.w, f, a.w);
        arow[lane] = a;
        if (last) {
            float4 o4 = make_float4(a.x * 0.25f, a.y * 0.25f,
                                    a.z * 0.25f, a.w * 0.25f);
            *reinterpret_cast<float4*>(&out[(size_t)r * E + lane * 4]) = o4;
        }
    }
}

// ---------------------------------------------------------------------------
extern "C" void kernel_launch(void* const* d_in, const int* in_sizes, int n_in,
                              void* d_out, int out_size) {
    const float* emb   = (const float*)d_in[0];     // [100000,112]
    const float* D     = (const float*)d_in[1];     // [4096,4096]
    const float* A     = (const float*)d_in[2];     // [4096,4096]
    const float* slen  = (const float*)d_in[3];     // [4096,1]
    const float* Ws    = (const float*)d_in[4];     // [3,112,112]
    const int*   items = (const int*)d_in[5];       // [4096,200] int32
    float* out = (float*)d_out;

    cudaFuncSetAttribute(big_mm_mma, cudaFuncAttributeMaxDynamicSharedMemorySize,
                         SMEM_BYTES);
    cudaFuncSetAttribute(small_mm_tc, cudaFuncAttributeMaxDynamicSharedMemorySize,
                         SM2_BYTES);

    prep_kernel<<<NB_PREP, PREP_T>>>(A, emb, items, slen, D);

    for (int l = 0; l < LAYERS; ++l) {
        small_mm_tc<<<128, 128, SM2_BYTES>>>(Ws + (size_t)l * E * E);
        big_mm_mma<<<dim3(B_SESS / 128, KSPLIT), 256, SMEM_BYTES>>>();
        reduce_norm_kernel<<<B_SESS / 8, 256>>>(out, l == LAYERS - 1);
    }
}

// round 15
// speedup vs baseline: 1.4959x; 1.4959x over previous
#include <cuda_runtime.h>
#include <cuda_fp16.h>
#include <cstdint>

#define B_SESS 4096
#define MAX_LEN 200
#define E 112
#define N_ITEMS 100000
#define LAYERS 3
#define KSPLIT 8
#define KCHUNK (B_SESS / KSPLIT)   // 512
#define BK 32
#define NSTAGE (KCHUNK / BK)       // 16

// big_mm smem (halves): strides conflict-free for half2 fragment LDS.
#define AS_H 40
#define BS_H 40
#define A_STAGE_H (128 * AS_H)     // 5120 halves
#define B_STAGE_H (E * BS_H)       // 4480 halves
#define SMEM_BYTES ((2 * A_STAGE_H + 2 * B_STAGE_H) * 2)   // 38400

// small_mm smem: S tile [32][116], W^T [112][120] (tf32 bits)
#define SS_STRIDE 116
#define WS_STRIDE 120
#define SM2_BYTES ((32 * SS_STRIDE + 112 * WS_STRIDE) * 4)   // 68608

// prep grid partition (448 threads/CTA): gather || A->fp16 || diag
#define NB_GATHER 4096
#define NB_CVTA   4682               // ceil(16777216 / (448*8))
#define NB_DIAG   10
#define NB_PREP   (NB_GATHER + NB_CVTA + NB_DIAG)

// Scratch
__device__ __half g_Ah[(size_t)B_SESS * B_SESS];     // A in fp16
__device__ __half g_tT[(size_t)E * B_SESS];          // (s @ W^T)^T fp16 [112,4096]
__device__ float g_s[B_SESS * E];
__device__ float g_acc[B_SESS * E];
__device__ __half g_part[(size_t)KSPLIT * B_SESS * E];  // fp16 split-K partials
__device__ float g_d[B_SESS];

// ---------------------------------------------------------------------------
// PTX helpers (plain sm_80+; no arch-'a' gating)
// ---------------------------------------------------------------------------
__device__ __forceinline__ uint32_t smem_u32(const void* p) {
    uint32_t a;
    asm("{ .reg .u64 t; cvta.to.shared.u64 t, %1; cvt.u32.u64 %0, t; }"
        : "=r"(a) : "l"(p));
    return a;
}
__device__ __forceinline__ uint32_t f2tf32(float f) {
    uint32_t u;
    asm("cvt.rn.tf32.f32 %0, %1;" : "=r"(u) : "f"(f));
    return u;
}
#define CP16(dst, src) \
    asm volatile("cp.async.cg.shared.global [%0], [%1], 16;" \
                 :: "r"(dst), "l"(src) : "memory")
#define CP_COMMIT() asm volatile("cp.async.commit_group;" ::: "memory")
#define CP_WAIT1()  asm volatile("cp.async.wait_group 1;" ::: "memory")
#define CP_WAIT0()  asm volatile("cp.async.wait_group 0;" ::: "memory")

// tf32 k8 mma (small_mm)
__device__ __forceinline__ void mma_tf32(float* c, const uint32_t* a,
                                         const uint32_t* b) {
    asm volatile(
        "mma.sync.aligned.m16n8k8.row.col.f32.tf32.tf32.f32 "
        "{%0,%1,%2,%3},{%4,%5,%6,%7},{%8,%9},{%0,%1,%2,%3};"
        : "+f"(c[0]), "+f"(c[1]), "+f"(c[2]), "+f"(c[3])
        : "r"(a[0]), "r"(a[1]), "r"(a[2]), "r"(a[3]), "r"(b[0]), "r"(b[1]));
}
// fp16 k16 mma (big_mm)
__device__ __forceinline__ void mma_f16(float* c, const uint32_t* a,
                                        const uint32_t* b) {
    asm volatile(
        "mma.sync.aligned.m16n8k16.row.col.f32.f16.f16.f32 "
        "{%0,%1,%2,%3},{%4,%5,%6,%7},{%8,%9},{%0,%1,%2,%3};"
        : "+f"(c[0]), "+f"(c[1]), "+f"(c[2]), "+f"(c[3])
        : "r"(a[0]), "r"(a[1]), "r"(a[2]), "r"(a[3]), "r"(b[0]), "r"(b[1]));
}

// ---------------------------------------------------------------------------
// 1. Prep: gather+mean (fp32 table, 4-way split) || A->fp16 || diag.
// ---------------------------------------------------------------------------
__global__ void __launch_bounds__(448)
prep_kernel(const float* __restrict__ A,
            const float* __restrict__ emb,
            const int* __restrict__ items,
            const float* __restrict__ slen,
            const float* __restrict__ D) {
    int blk = blockIdx.x;
    int tid = threadIdx.x;

    if (blk < NB_GATHER) {                       // ---- gather + mean pool ----
        __shared__ int sidx[MAX_LEN];
        __shared__ float partial[3][E];
        int b = blk;
        for (int i = tid; i < MAX_LEN; i += blockDim.x)
            sidx[i] = items[(size_t)b * MAX_LEN + i];
        __syncthreads();
        int q = tid / E;                         // quarter 0..3
        int col = tid - q * E;
        float acc = 0.0f;
        {
            int t0 = q * (MAX_LEN / 4);
            int t1 = t0 + (MAX_LEN / 4);
            #pragma unroll 5
            for (int t = t0; t < t1; ++t) {
                int idx = sidx[t];
                if (idx > 0 && idx <= N_ITEMS)
                    acc += emb[((size_t)(idx - 1)) * E + col];
            }
        }
        if (q > 0) partial[q - 1][col] = acc;
        __syncthreads();
        if (q == 0) {
            float v = (acc + partial[0][col] + partial[1][col] +
                       partial[2][col]) / slen[b];
            g_s[(size_t)b * E + col] = v;
            g_acc[(size_t)b * E + col] = v;
        }
    } else if (blk < NB_GATHER + NB_CVTA) {      // ---- A -> fp16 ----
        size_t i = (((size_t)(blk - NB_GATHER)) * 448 + tid) * 8;
        if (i < (size_t)B_SESS * B_SESS) {
            float4 a = *reinterpret_cast<const float4*>(A + i);
            float4 b = *reinterpret_cast<const float4*>(A + i + 4);
            __half2 h0 = __floats2half2_rn(a.x, a.y);
            __half2 h1 = __floats2half2_rn(a.z, a.w);
            __half2 h2 = __floats2half2_rn(b.x, b.y);
            __half2 h3 = __floats2half2_rn(b.z, b.w);
            uint4 u;
            u.x = *reinterpret_cast<uint32_t*>(&h0);
            u.y = *reinterpret_cast<uint32_t*>(&h1);
            u.z = *reinterpret_cast<uint32_t*>(&h2);
            u.w = *reinterpret_cast<uint32_t*>(&h3);
            *reinterpret_cast<uint4*>(&g_Ah[i]) = u;
        }
    } else {                                     // ---- diag(D) ----
        int i = (blk - NB_GATHER - NB_CVTA) * 448 + tid;
        if (i < B_SESS)
            g_d[i] = D[(size_t)i * B_SESS + i];
    }
}

// ---------------------------------------------------------------------------
// 2. small GEMM (tf32 tensor cores): g_tT = fp16((g_s @ W^T)^T)
//    grid 128 x 128 thr (4 warps: 2(M) x 2(N)). M=32/CTA, N=112, K=112.
// ---------------------------------------------------------------------------
__global__ void __launch_bounds__(128)
small_mm_tc(const float* __restrict__ W) {
    extern __shared__ uint32_t sm2[];
    uint32_t* Ss = sm2;                          // [32][SS_STRIDE]
    uint32_t* Wt = sm2 + 32 * SS_STRIDE;         // [112][WS_STRIDE] (k-major)

    const int tid = threadIdx.x;
    const int lane = tid & 31;
    const int wid = tid >> 5;
    const int wm = wid & 1;
    const int wn = wid >> 1;
    const int g = lane >> 2;
    const int t = lane & 3;
    const int row0 = blockIdx.x * 32;

    for (int idx = tid; idx < 32 * (E / 4); idx += 128) {
        int r = idx / (E / 4), c4 = idx % (E / 4);
        float4 v = *reinterpret_cast<const float4*>(
            &g_s[(size_t)(row0 + r) * E + c4 * 4]);
        uint32_t* dst = &Ss[r * SS_STRIDE + c4 * 4];
        dst[0] = f2tf32(v.x); dst[1] = f2tf32(v.y);
        dst[2] = f2tf32(v.z); dst[3] = f2tf32(v.w);
    }
    for (int idx = tid; idx < E * (E / 4); idx += 128) {
        int o = idx / (E / 4), i4 = idx % (E / 4);
        float4 v = *reinterpret_cast<const float4*>(&W[(size_t)o * E + i4 * 4]);
        Wt[(i4 * 4 + 0) * WS_STRIDE + o] = f2tf32(v.x);
        Wt[(i4 * 4 + 1) * WS_STRIDE + o] = f2tf32(v.y);
        Wt[(i4 * 4 + 2) * WS_STRIDE + o] = f2tf32(v.z);
        Wt[(i4 * 4 + 3) * WS_STRIDE + o] = f2tf32(v.w);
    }
    __syncthreads();

    float acc[7][4];
    #pragma unroll
    for (int j = 0; j < 7; ++j)
        #pragma unroll
        for (int k = 0; k < 4; ++k) acc[j][k] = 0.0f;

    #pragma unroll
    for (int ks = 0; ks < 14; ++ks) {
        uint32_t a[4], b[7][2];
        {
            int r = wm * 16 + g;
            int c = ks * 8 + t;
            a[0] = Ss[r * SS_STRIDE + c];
            a[1] = Ss[(r + 8) * SS_STRIDE + c];
            a[2] = Ss[r * SS_STRIDE + c + 4];
            a[3] = Ss[(r + 8) * SS_STRIDE + c + 4];
        }
        #pragma unroll
        for (int j = 0; j < 7; ++j) {
            int n = wn * 56 + j * 8 + g;
            int r = ks * 8 + t;
            b[j][0] = Wt[r * WS_STRIDE + n];
            b[j][1] = Wt[(r + 4) * WS_STRIDE + n];
        }
        #pragma unroll
        for (int j = 0; j < 7; ++j)
            mma_tf32(acc[j], a, b[j]);
    }

    // transposed fp16 store: g_tT[n][k]  (k = session row)
    {
        int r = row0 + wm * 16 + g;
        #pragma unroll
        for (int j = 0; j < 7; ++j) {
            int n = wn * 56 + j * 8 + 2 * t;
            g_tT[(size_t)n * B_SESS + r]           = __float2half(acc[j][0]);
            g_tT[(size_t)(n + 1) * B_SESS + r]     = __float2half(acc[j][1]);
            g_tT[(size_t)n * B_SESS + r + 8]       = __float2half(acc[j][2]);
            g_tT[(size_t)(n + 1) * B_SESS + r + 8] = __float2half(acc[j][3]);
        }
    }
}

// ---------------------------------------------------------------------------
// 3. Big fp16 tensor-core GEMM: part[split] = A[:, kc] @ t[kc, :]
//    m16n8k16.f16, fp32 accumulate, fp16 partial stores. 2-stage cp.async.
// ---------------------------------------------------------------------------
__global__ void __launch_bounds__(256)
big_mm_mma() {
    extern __shared__ __half smemh[];
    __half* As = smemh;                      // [2][128][AS_H]
    __half* Bs = smemh + 2 * A_STAGE_H;      // [2][112][BS_H]

    const int tid = threadIdx.x;
    const int lane = tid & 31;
    const int wid = tid >> 5;
    const int wm = wid & 3;
    const int wn = wid >> 2;
    const int g = lane >> 2;
    const int t = lane & 3;
    const int row0 = blockIdx.x * 128;
    const int kbase = blockIdx.y * KCHUNK;

    float acc[2][7][4];
    #pragma unroll
    for (int i = 0; i < 2; ++i)
        #pragma unroll
        for (int j = 0; j < 7; ++j)
            #pragma unroll
            for (int k = 0; k < 4; ++k) acc[i][j][k] = 0.0f;

    auto stage = [&](int buf, int k0) {
        __half* Ab = As + buf * A_STAGE_H;
        __half* Bb = Bs + buf * B_STAGE_H;
        #pragma unroll
        for (int j = 0; j < 2; ++j) {          // A: 512 16B chunks
            int c = tid + j * 256;
            int r = c >> 2, cc = c & 3;
            uint32_t dst = smem_u32(&Ab[r * AS_H + cc * 8]);
            CP16(dst, &g_Ah[(size_t)(row0 + r) * B_SESS + k0 + cc * 8]);
        }
        #pragma unroll
        for (int j = 0; j < 2; ++j) {          // B: 448 16B chunks
            int c = tid + j * 256;
            if (c < 448) {
                int n = c >> 2, cc = c & 3;
                uint32_t dst = smem_u32(&Bb[n * BS_H + cc * 8]);
                CP16(dst, &g_tT[(size_t)n * B_SESS + k0 + cc * 8]);
            }
        }
    };

    auto compute = [&](int buf) {
        const __half* A_ = As + buf * A_STAGE_H;
        const __half* B_ = Bs + buf * B_STAGE_H;
        #pragma unroll
        for (int ks = 0; ks < 2; ++ks) {       // BK=32 -> 2 x K=16
            uint32_t a[2][4], b[7][2];
            #pragma unroll
            for (int i = 0; i < 2; ++i) {
                int r = wm * 32 + i * 16 + g;
                int c = ks * 16 + t * 2;
                a[i][0] = *reinterpret_cast<const uint32_t*>(&A_[r * AS_H + c]);
                a[i][1] = *reinterpret_cast<const uint32_t*>(&A_[(r + 8) * AS_H + c]);
                a[i][2] = *reinterpret_cast<const uint32_t*>(&A_[r * AS_H + c + 8]);
                a[i][3] = *reinterpret_cast<const uint32_t*>(&A_[(r + 8) * AS_H + c + 8]);
            }
            #pragma unroll
            for (int j = 0; j < 7; ++j) {
                int n = wn * 56 + j * 8 + g;
                int c = ks * 16 + t * 2;
                b[j][0] = *reinterpret_cast<const uint32_t*>(&B_[n * BS_H + c]);
                b[j][1] = *reinterpret_cast<const uint32_t*>(&B_[n * BS_H + c + 8]);
            }
            #pragma unroll
            for (int i = 0; i < 2; ++i)
                #pragma unroll
                for (int j = 0; j < 7; ++j)
                    mma_f16(acc[i][j], a[i], b[j]);
        }
    };

    stage(0, kbase);
    CP_COMMIT();
    for (int s = 0; s < NSTAGE; ++s) {
        if (s + 1 < NSTAGE) {
            stage((s + 1) & 1, kbase + (s + 1) * BK);
            CP_COMMIT();
            CP_WAIT1();
        } else {
            CP_WAIT0();
        }
        __syncthreads();
        compute(s & 1);
        __syncthreads();
    }

    // fp16 partial stores (half2 per n-pair)
    __half* part = g_part + (size_t)blockIdx.y * B_SESS * E;
    #pragma unroll
    for (int i = 0; i < 2; ++i) {
        int r = row0 + wm * 32 + i * 16 + g;
        #pragma unroll
        for (int j = 0; j < 7; ++j) {
            int n = wn * 56 + j * 8 + 2 * t;
            *reinterpret_cast<__half2*>(&part[(size_t)r * E + n]) =
                __floats2half2_rn(acc[i][j][0], acc[i][j][1]);
            *reinterpret_cast<__half2*>(&part[(size_t)(r + 8) * E + n]) =
                __floats2half2_rn(acc[i][j][2], acc[i][j][3]);
        }
    }
}

// ---------------------------------------------------------------------------
// 4. Fused: split-K reduce (fp16 partials, uint4 loads) + diag scale +
//    L2-normalize + acc (+ final out). One warp per row; grid = 512.
// ---------------------------------------------------------------------------
__global__ void reduce_norm_kernel(float* __restrict__ out, int last) {
    int warp = threadIdx.x >> 5;
    int lane = threadIdx.x & 31;
    int r = blockIdx.x * 8 + warp;

    // 14 active lanes, 8 columns each (16B fp16 loads)
    float v[8] = {0.f, 0.f, 0.f, 0.f, 0.f, 0.f, 0.f, 0.f};
    if (lane < E / 8) {
        #pragma unroll
        for (int c = 0; c < KSPLIT; ++c) {
            uint4 u = *reinterpret_cast<const uint4*>(
                &g_part[(size_t)c * B_SESS * E + (size_t)r * E + lane * 8]);
            float2 p0 = __half22float2(*reinterpret_cast<__half2*>(&u.x));
            float2 p1 = __half22float2(*reinterpret_cast<__half2*>(&u.y));
            float2 p2 = __half22float2(*reinterpret_cast<__half2*>(&u.z));
            float2 p3 = __half22float2(*reinterpret_cast<__half2*>(&u.w));
            v[0] += p0.x; v[1] += p0.y; v[2] += p1.x; v[3] += p1.y;
            v[4] += p2.x; v[5] += p2.y; v[6] += p3.x; v[7] += p3.y;
        }
        float d = g_d[r];
        #pragma unroll
        for (int k = 0; k < 8; ++k) v[k] *= d;
        float4* srow = reinterpret_cast<float4*>(&g_s[(size_t)r * E + lane * 8]);
        srow[0] = make_float4(v[0], v[1], v[2], v[3]);
        srow[1] = make_float4(v[4], v[5], v[6], v[7]);
    }
    float ss = 0.f;
    #pragma unroll
    for (int k = 0; k < 8; ++k) ss += v[k] * v[k];
    #pragma unroll
    for (int o = 16; o; o >>= 1) ss += __shfl_xor_sync(0xffffffffu, ss, o);
    float f = 1.0f / fmaxf(sqrtf(ss), 1e-12f);
    if (lane < E / 8) {
        float4* arow = reinterpret_cast<float4*>(g_acc + (size_t)r * E + lane * 8);
        float4 a0 = arow[0], a1 = arow[1];
        a0.x = fmaf(v[0], f, a0.x); a0.y = fmaf(v[1], f, a0.y);
        a0.z = fmaf(v[2], f, a0.z); a0.w = fmaf(v[3], f, a0.w);
        a1.x = fmaf(v[4], f, a1.x); a1.y = fmaf(v[5], f, a1.y);
        a1.z = fmaf(v[6], f, a1.z); a1.w = fmaf(v[7], f, a1.w);
        arow[0] = a0; arow[1] = a1;
        if (last) {
            float4* orow = reinterpret_cast<float4*>(&out[(size_t)r * E + lane * 8]);
            orow[0] = make_float4(a0.x * 0.25f, a0.y * 0.25f,
                                  a0.z * 0.25f, a0.w * 0.25f);
            orow[1] = make_float4(a1.x * 0.25f, a1.y * 0.25f,
                                  a1.z * 0.25f, a1.w * 0.25f);
        }
    }
}

// ---------------------------------------------------------------------------
extern "C" void kernel_launch(void* const* d_in, const int* in_sizes, int n_in,
                              void* d_out, int out_size) {
    const float* emb   = (const float*)d_in[0];     // [100000,112]
    const float* D     = (const float*)d_in[1];     // [4096,4096]
    const float* A     = (const float*)d_in[2];     // [4096,4096]
    const float* slen  = (const float*)d_in[3];     // [4096,1]
    const float* Ws    = (const float*)d_in[4];     // [3,112,112]
    const int*   items = (const int*)d_in[5];       // [4096,200] int32
    float* out = (float*)d_out;

    cudaFuncSetAttribute(big_mm_mma, cudaFuncAttributeMaxDynamicSharedMemorySize,
                         SMEM_BYTES);
    cudaFuncSetAttribute(small_mm_tc, cudaFuncAttributeMaxDynamicSharedMemorySize,
                         SM2_BYTES);

    prep_kernel<<<NB_PREP, 448>>>(A, emb, items, slen, D);

    for (int l = 0; l < LAYERS; ++l) {
        small_mm_tc<<<128, 128, SM2_BYTES>>>(Ws + (size_t)l * E * E);
        big_mm_mma<<<dim3(B_SESS / 128, KSPLIT), 256, SMEM_BYTES>>>();
        reduce_norm_kernel<<<B_SESS / 8, 256>>>(out, l == LAYERS - 1);
    }
}

// round 16
// speedup vs baseline: 1.6198x; 1.0828x over previous
#include <cuda_runtime.h>
#include <cuda_fp16.h>
#include <cstdint>

#define B_SESS 4096
#define MAX_LEN 200
#define E 112
#define N_ITEMS 100000
#define LAYERS 3
#define KSPLIT 8
#define KCHUNK (B_SESS / KSPLIT)   // 512
#define BK 32
#define NSTAGE (KCHUNK / BK)       // 16

// big_mm smem (halves): strides conflict-free for half2 fragment LDS.
#define AS_H 40
#define BS_H 40
#define A_STAGE_H (128 * AS_H)     // 5120 halves
#define B_STAGE_H (E * BS_H)       // 4480 halves
#define SMEM_BYTES ((2 * A_STAGE_H + 2 * B_STAGE_H) * 2)   // 38400

// small_mm smem: S tile [32][116], W^T [112][120] (tf32 bits)
#define SS_STRIDE 116
#define WS_STRIDE 120
#define SM2_BYTES ((32 * SS_STRIDE + 112 * WS_STRIDE) * 4)   // 68608

// prep grid partition (448 threads/CTA): gather || A->fp16 || diag
#define NB_GATHER 4096
#define NB_CVTA   4682               // ceil(16777216 / (448*8))
#define NB_DIAG   10
#define NB_PREP   (NB_GATHER + NB_CVTA + NB_DIAG)

// gather: 16 time-groups x 28 float4-columns
#define GQ 16
#define GC 28

// Scratch
__device__ __half g_Ah[(size_t)B_SESS * B_SESS];     // A in fp16
__device__ __half g_tT[(size_t)E * B_SESS];          // (s @ W^T)^T fp16 [112,4096]
__device__ float g_s[B_SESS * E];
__device__ float g_acc[B_SESS * E];
__device__ __half g_part[(size_t)KSPLIT * B_SESS * E];  // fp16 split-K partials
__device__ float g_d[B_SESS];

// ---------------------------------------------------------------------------
// PTX helpers (plain sm_80+; no arch-'a' gating)
// ---------------------------------------------------------------------------
__device__ __forceinline__ uint32_t smem_u32(const void* p) {
    uint32_t a;
    asm("{ .reg .u64 t; cvta.to.shared.u64 t, %1; cvt.u32.u64 %0, t; }"
        : "=r"(a) : "l"(p));
    return a;
}
__device__ __forceinline__ uint32_t f2tf32(float f) {
    uint32_t u;
    asm("cvt.rn.tf32.f32 %0, %1;" : "=r"(u) : "f"(f));
    return u;
}
#define CP16(dst, src) \
    asm volatile("cp.async.cg.shared.global [%0], [%1], 16;" \
                 :: "r"(dst), "l"(src) : "memory")
#define CP_COMMIT() asm volatile("cp.async.commit_group;" ::: "memory")
#define CP_WAIT1()  asm volatile("cp.async.wait_group 1;" ::: "memory")
#define CP_WAIT0()  asm volatile("cp.async.wait_group 0;" ::: "memory")

// tf32 k8 mma (small_mm)
__device__ __forceinline__ void mma_tf32(float* c, const uint32_t* a,
                                         const uint32_t* b) {
    asm volatile(
        "mma.sync.aligned.m16n8k8.row.col.f32.tf32.tf32.f32 "
        "{%0,%1,%2,%3},{%4,%5,%6,%7},{%8,%9},{%0,%1,%2,%3};"
        : "+f"(c[0]), "+f"(c[1]), "+f"(c[2]), "+f"(c[3])
        : "r"(a[0]), "r"(a[1]), "r"(a[2]), "r"(a[3]), "r"(b[0]), "r"(b[1]));
}
// fp16 k16 mma (big_mm)
__device__ __forceinline__ void mma_f16(float* c, const uint32_t* a,
                                        const uint32_t* b) {
    asm volatile(
        "mma.sync.aligned.m16n8k16.row.col.f32.f16.f16.f32 "
        "{%0,%1,%2,%3},{%4,%5,%6,%7},{%8,%9},{%0,%1,%2,%3};"
        : "+f"(c[0]), "+f"(c[1]), "+f"(c[2]), "+f"(c[3])
        : "r"(a[0]), "r"(a[1]), "r"(a[2]), "r"(a[3]), "r"(b[0]), "r"(b[1]));
}

// ---------------------------------------------------------------------------
// 1. Prep: gather+mean (float4 rows, 16-way time split) || A->fp16 || diag.
// ---------------------------------------------------------------------------
__global__ void __launch_bounds__(448)
prep_kernel(const float* __restrict__ A,
            const float* __restrict__ emb,
            const int* __restrict__ items,
            const float* __restrict__ slen,
            const float* __restrict__ D) {
    int blk = blockIdx.x;
    int tid = threadIdx.x;

    if (blk < NB_GATHER) {                       // ---- gather + mean pool ----
        __shared__ int sidx[MAX_LEN];
        __shared__ float4 part4[GQ][GC];
        int b = blk;
        for (int i = tid; i < MAX_LEN; i += 448)
            sidx[i] = items[(size_t)b * MAX_LEN + i];
        __syncthreads();
        int g = tid / GC;                        // time group 0..15
        int c4 = tid - g * GC;                   // float4 column 0..27
        float4 acc = make_float4(0.f, 0.f, 0.f, 0.f);
        int t0 = (MAX_LEN * g) >> 4;
        int t1 = (MAX_LEN * (g + 1)) >> 4;
        for (int t = t0; t < t1; ++t) {
            int idx = sidx[t];
            if (idx > 0 && idx <= N_ITEMS) {
                float4 v = *reinterpret_cast<const float4*>(
                    &emb[((size_t)(idx - 1)) * E + c4 * 4]);
                acc.x += v.x; acc.y += v.y; acc.z += v.z; acc.w += v.w;
            }
        }
        part4[g][c4] = acc;
        __syncthreads();
        if (tid < GC) {
            float4 s = part4[0][tid];
            #pragma unroll
            for (int j = 1; j < GQ; ++j) {
                float4 p = part4[j][tid];
                s.x += p.x; s.y += p.y; s.z += p.z; s.w += p.w;
            }
            float inv = 1.0f / slen[b];
            s.x *= inv; s.y *= inv; s.z *= inv; s.w *= inv;
            *reinterpret_cast<float4*>(&g_s[(size_t)b * E + tid * 4]) = s;
            *reinterpret_cast<float4*>(&g_acc[(size_t)b * E + tid * 4]) = s;
        }
    } else if (blk < NB_GATHER + NB_CVTA) {      // ---- A -> fp16 ----
        size_t i = (((size_t)(blk - NB_GATHER)) * 448 + tid) * 8;
        if (i < (size_t)B_SESS * B_SESS) {
            float4 a = *reinterpret_cast<const float4*>(A + i);
            float4 b = *reinterpret_cast<const float4*>(A + i + 4);
            __half2 h0 = __floats2half2_rn(a.x, a.y);
            __half2 h1 = __floats2half2_rn(a.z, a.w);
            __half2 h2 = __floats2half2_rn(b.x, b.y);
            __half2 h3 = __floats2half2_rn(b.z, b.w);
            uint4 u;
            u.x = *reinterpret_cast<uint32_t*>(&h0);
            u.y = *reinterpret_cast<uint32_t*>(&h1);
            u.z = *reinterpret_cast<uint32_t*>(&h2);
            u.w = *reinterpret_cast<uint32_t*>(&h3);
            *reinterpret_cast<uint4*>(&g_Ah[i]) = u;
        }
    } else {                                     // ---- diag(D) ----
        int i = (blk - NB_GATHER - NB_CVTA) * 448 + tid;
        if (i < B_SESS)
            g_d[i] = D[(size_t)i * B_SESS + i];
    }
}

// ---------------------------------------------------------------------------
// 2. small GEMM (tf32 tensor cores): g_tT = fp16((g_s @ W^T)^T)
//    grid 128 x 128 thr (4 warps: 2(M) x 2(N)). M=32/CTA, N=112, K=112.
// ---------------------------------------------------------------------------
__global__ void __launch_bounds__(128)
small_mm_tc(const float* __restrict__ W) {
    extern __shared__ uint32_t sm2[];
    uint32_t* Ss = sm2;                          // [32][SS_STRIDE]
    uint32_t* Wt = sm2 + 32 * SS_STRIDE;         // [112][WS_STRIDE] (k-major)

    const int tid = threadIdx.x;
    const int lane = tid & 31;
    const int wid = tid >> 5;
    const int wm = wid & 1;
    const int wn = wid >> 1;
    const int g = lane >> 2;
    const int t = lane & 3;
    const int row0 = blockIdx.x * 32;

    for (int idx = tid; idx < 32 * (E / 4); idx += 128) {
        int r = idx / (E / 4), c4 = idx % (E / 4);
        float4 v = *reinterpret_cast<const float4*>(
            &g_s[(size_t)(row0 + r) * E + c4 * 4]);
        uint32_t* dst = &Ss[r * SS_STRIDE + c4 * 4];
        dst[0] = f2tf32(v.x); dst[1] = f2tf32(v.y);
        dst[2] = f2tf32(v.z); dst[3] = f2tf32(v.w);
    }
    for (int idx = tid; idx < E * (E / 4); idx += 128) {
        int o = idx / (E / 4), i4 = idx % (E / 4);
        float4 v = *reinterpret_cast<const float4*>(&W[(size_t)o * E + i4 * 4]);
        Wt[(i4 * 4 + 0) * WS_STRIDE + o] = f2tf32(v.x);
        Wt[(i4 * 4 + 1) * WS_STRIDE + o] = f2tf32(v.y);
        Wt[(i4 * 4 + 2) * WS_STRIDE + o] = f2tf32(v.z);
        Wt[(i4 * 4 + 3) * WS_STRIDE + o] = f2tf32(v.w);
    }
    __syncthreads();

    float acc[7][4];
    #pragma unroll
    for (int j = 0; j < 7; ++j)
        #pragma unroll
        for (int k = 0; k < 4; ++k) acc[j][k] = 0.0f;

    #pragma unroll
    for (int ks = 0; ks < 14; ++ks) {
        uint32_t a[4], b[7][2];
        {
            int r = wm * 16 + g;
            int c = ks * 8 + t;
            a[0] = Ss[r * SS_STRIDE + c];
            a[1] = Ss[(r + 8) * SS_STRIDE + c];
            a[2] = Ss[r * SS_STRIDE + c + 4];
            a[3] = Ss[(r + 8) * SS_STRIDE + c + 4];
        }
        #pragma unroll
        for (int j = 0; j < 7; ++j) {
            int n = wn * 56 + j * 8 + g;
            int r = ks * 8 + t;
            b[j][0] = Wt[r * WS_STRIDE + n];
            b[j][1] = Wt[(r + 4) * WS_STRIDE + n];
        }
        #pragma unroll
        for (int j = 0; j < 7; ++j)
            mma_tf32(acc[j], a, b[j]);
    }

    // transposed fp16 store: g_tT[n][k]  (k = session row)
    {
        int r = row0 + wm * 16 + g;
        #pragma unroll
        for (int j = 0; j < 7; ++j) {
            int n = wn * 56 + j * 8 + 2 * t;
            g_tT[(size_t)n * B_SESS + r]           = __float2half(acc[j][0]);
            g_tT[(size_t)(n + 1) * B_SESS + r]     = __float2half(acc[j][1]);
            g_tT[(size_t)n * B_SESS + r + 8]       = __float2half(acc[j][2]);
            g_tT[(size_t)(n + 1) * B_SESS + r + 8] = __float2half(acc[j][3]);
        }
    }
}

// ---------------------------------------------------------------------------
// 3. Big fp16 tensor-core GEMM: part[split] = A[:, kc] @ t[kc, :]
//    m16n8k16.f16, fp32 accumulate, fp16 partial stores. 2-stage cp.async.
// ---------------------------------------------------------------------------
__global__ void __launch_bounds__(256)
big_mm_mma() {
    extern __shared__ __half smemh[];
    __half* As = smemh;                      // [2][128][AS_H]
    __half* Bs = smemh + 2 * A_STAGE_H;      // [2][112][BS_H]

    const int tid = threadIdx.x;
    const int lane = tid & 31;
    const int wid = tid >> 5;
    const int wm = wid & 3;
    const int wn = wid >> 2;
    const int g = lane >> 2;
    const int t = lane & 3;
    const int row0 = blockIdx.x * 128;
    const int kbase = blockIdx.y * KCHUNK;

    float acc[2][7][4];
    #pragma unroll
    for (int i = 0; i < 2; ++i)
        #pragma unroll
        for (int j = 0; j < 7; ++j)
            #pragma unroll
            for (int k = 0; k < 4; ++k) acc[i][j][k] = 0.0f;

    auto stage = [&](int buf, int k0) {
        __half* Ab = As + buf * A_STAGE_H;
        __half* Bb = Bs + buf * B_STAGE_H;
        #pragma unroll
        for (int j = 0; j < 2; ++j) {          // A: 512 16B chunks
            int c = tid + j * 256;
            int r = c >> 2, cc = c & 3;
            uint32_t dst = smem_u32(&Ab[r * AS_H + cc * 8]);
            CP16(dst, &g_Ah[(size_t)(row0 + r) * B_SESS + k0 + cc * 8]);
        }
        #pragma unroll
        for (int j = 0; j < 2; ++j) {          // B: 448 16B chunks
            int c = tid + j * 256;
            if (c < 448) {
                int n = c >> 2, cc = c & 3;
                uint32_t dst = smem_u32(&Bb[n * BS_H + cc * 8]);
                CP16(dst, &g_tT[(size_t)n * B_SESS + k0 + cc * 8]);
            }
        }
    };

    auto compute = [&](int buf) {
        const __half* A_ = As + buf * A_STAGE_H;
        const __half* B_ = Bs + buf * B_STAGE_H;
        #pragma unroll
        for (int ks = 0; ks < 2; ++ks) {       // BK=32 -> 2 x K=16
            uint32_t a[2][4], b[7][2];
            #pragma unroll
            for (int i = 0; i < 2; ++i) {
                int r = wm * 32 + i * 16 + g;
                int c = ks * 16 + t * 2;
                a[i][0] = *reinterpret_cast<const uint32_t*>(&A_[r * AS_H + c]);
                a[i][1] = *reinterpret_cast<const uint32_t*>(&A_[(r + 8) * AS_H + c]);
                a[i][2] = *reinterpret_cast<const uint32_t*>(&A_[r * AS_H + c + 8]);
                a[i][3] = *reinterpret_cast<const uint32_t*>(&A_[(r + 8) * AS_H + c + 8]);
            }
            #pragma unroll
            for (int j = 0; j < 7; ++j) {
                int n = wn * 56 + j * 8 + g;
                int c = ks * 16 + t * 2;
                b[j][0] = *reinterpret_cast<const uint32_t*>(&B_[n * BS_H + c]);
                b[j][1] = *reinterpret_cast<const uint32_t*>(&B_[n * BS_H + c + 8]);
            }
            #pragma unroll
            for (int i = 0; i < 2; ++i)
                #pragma unroll
                for (int j = 0; j < 7; ++j)
                    mma_f16(acc[i][j], a[i], b[j]);
        }
    };

    stage(0, kbase);
    CP_COMMIT();
    for (int s = 0; s < NSTAGE; ++s) {
        if (s + 1 < NSTAGE) {
            stage((s + 1) & 1, kbase + (s + 1) * BK);
            CP_COMMIT();
            CP_WAIT1();
        } else {
            CP_WAIT0();
        }
        __syncthreads();
        compute(s & 1);
        __syncthreads();
    }

    // fp16 partial stores (half2 per n-pair)
    __half* part = g_part + (size_t)blockIdx.y * B_SESS * E;
    #pragma unroll
    for (int i = 0; i < 2; ++i) {
        int r = row0 + wm * 32 + i * 16 + g;
        #pragma unroll
        for (int j = 0; j < 7; ++j) {
            int n = wn * 56 + j * 8 + 2 * t;
            *reinterpret_cast<__half2*>(&part[(size_t)r * E + n]) =
                __floats2half2_rn(acc[i][j][0], acc[i][j][1]);
            *reinterpret_cast<__half2*>(&part[(size_t)(r + 8) * E + n]) =
                __floats2half2_rn(acc[i][j][2], acc[i][j][3]);
        }
    }
}

// ---------------------------------------------------------------------------
// 4. Fused: split-K reduce (fp16 partials, uint4 loads) + diag scale +
//    L2-normalize + acc (+ final out). One warp per row; grid = 512.
// ---------------------------------------------------------------------------
__global__ void reduce_norm_kernel(float* __restrict__ out, int last) {
    int warp = threadIdx.x >> 5;
    int lane = threadIdx.x & 31;
    int r = blockIdx.x * 8 + warp;

    // 14 active lanes, 8 columns each (16B fp16 loads)
    float v[8] = {0.f, 0.f, 0.f, 0.f, 0.f, 0.f, 0.f, 0.f};
    if (lane < E / 8) {
        #pragma unroll
        for (int c = 0; c < KSPLIT; ++c) {
            uint4 u = *reinterpret_cast<const uint4*>(
                &g_part[(size_t)c * B_SESS * E + (size_t)r * E + lane * 8]);
            float2 p0 = __half22float2(*reinterpret_cast<__half2*>(&u.x));
            float2 p1 = __half22float2(*reinterpret_cast<__half2*>(&u.y));
            float2 p2 = __half22float2(*reinterpret_cast<__half2*>(&u.z));
            float2 p3 = __half22float2(*reinterpret_cast<__half2*>(&u.w));
            v[0] += p0.x; v[1] += p0.y; v[2] += p1.x; v[3] += p1.y;
            v[4] += p2.x; v[5] += p2.y; v[6] += p3.x; v[7] += p3.y;
        }
        float d = g_d[r];
        #pragma unroll
        for (int k = 0; k < 8; ++k) v[k] *= d;
        float4* srow = reinterpret_cast<float4*>(&g_s[(size_t)r * E + lane * 8]);
        srow[0] = make_float4(v[0], v[1], v[2], v[3]);
        srow[1] = make_float4(v[4], v[5], v[6], v[7]);
    }
    float ss = 0.f;
    #pragma unroll
    for (int k = 0; k < 8; ++k) ss += v[k] * v[k];
    #pragma unroll
    for (int o = 16; o; o >>= 1) ss += __shfl_xor_sync(0xffffffffu, ss, o);
    float f = 1.0f / fmaxf(sqrtf(ss), 1e-12f);
    if (lane < E / 8) {
        float4* arow = reinterpret_cast<float4*>(g_acc + (size_t)r * E + lane * 8);
        float4 a0 = arow[0], a1 = arow[1];
        a0.x = fmaf(v[0], f, a0.x); a0.y = fmaf(v[1], f, a0.y);
        a0.z = fmaf(v[2], f, a0.z); a0.w = fmaf(v[3], f, a0.w);
        a1.x = fmaf(v[4], f, a1.x); a1.y = fmaf(v[5], f, a1.y);
        a1.z = fmaf(v[6], f, a1.z); a1.w = fmaf(v[7], f, a1.w);
        arow[0] = a0; arow[1] = a1;
        if (last) {
            float4* orow = reinterpret_cast<float4*>(&out[(size_t)r * E + lane * 8]);
            orow[0] = make_float4(a0.x * 0.25f, a0.y * 0.25f,
                                  a0.z * 0.25f, a0.w * 0.25f);
            orow[1] = make_float4(a1.x * 0.25f, a1.y * 0.25f,
                                  a1.z * 0.25f, a1.w * 0.25f);
        }
    }
}

// ---------------------------------------------------------------------------
extern "C" void kernel_launch(void* const* d_in, const int* in_sizes, int n_in,
                              void* d_out, int out_size) {
    const float* emb   = (const float*)d_in[0];     // [100000,112]
    const float* D     = (const float*)d_in[1];     // [4096,4096]
    const float* A     = (const float*)d_in[2];     // [4096,4096]
    const float* slen  = (const float*)d_in[3];     // [4096,1]
    const float* Ws    = (const float*)d_in[4];     // [3,112,112]
    const int*   items = (const int*)d_in[5];       // [4096,200] int32
    float* out = (float*)d_out;

    cudaFuncSetAttribute(big_mm_mma, cudaFuncAttributeMaxDynamicSharedMemorySize,
                         SMEM_BYTES);
    cudaFuncSetAttribute(small_mm_tc, cudaFuncAttributeMaxDynamicSharedMemorySize,
                         SM2_BYTES);

    prep_kernel<<<NB_PREP, 448>>>(A, emb, items, slen, D);

    for (int l = 0; l < LAYERS; ++l) {
        small_mm_tc<<<128, 128, SM2_BYTES>>>(Ws + (size_t)l * E * E);
        big_mm_mma<<<dim3(B_SESS / 128, KSPLIT), 256, SMEM_BYTES>>>();
        reduce_norm_kernel<<<B_SESS / 8, 256>>>(out, l == LAYERS - 1);
    }
}